// round 8
// baseline (speedup 1.0000x reference)
#include <cuda_runtime.h>
#include <cstdint>

// ---------- hardware tanh (1 MUFU op); sigmoid via tanh identity ----------
__device__ __forceinline__ float tanh_(float x) {
    float r;
    asm("tanh.approx.f32 %0, %1;" : "=f"(r) : "f"(x));
    return r;
}
__device__ __forceinline__ float sig_(float x) {
    return fmaf(0.5f, tanh_(0.5f * x), 0.5f);
}

// volatile LDS.128: uncacheable, unhoistable -> kills ptxas weight-caching
__device__ __forceinline__ float4 lds128v(const float* p) {
    float4 v;
    unsigned saddr = (unsigned)__cvta_generic_to_shared(p);
    asm volatile("ld.volatile.shared.v4.f32 {%0,%1,%2,%3}, [%4];"
                 : "=f"(v.x), "=f"(v.y), "=f"(v.z), "=f"(v.w)
                 : "r"(saddr));
    return v;
}

#define TT 14
#define HH 7
#define FF 12
#define NTHR 128
#define EB 4            // batch elements per thread
#define BPB (NTHR * EB) // batch elements per block = 512

__global__ __launch_bounds__(NTHR)
void lstm_fused_kernel(
    const float* __restrict__ x,
    const float* __restrict__ w1,  const float* __restrict__ b1,
    const float* __restrict__ wih0, const float* __restrict__ whh0,
    const float* __restrict__ bih0, const float* __restrict__ bhh0,
    const float* __restrict__ wih1, const float* __restrict__ whh1,
    const float* __restrict__ bih1, const float* __restrict__ bhh1,
    const float* __restrict__ w2,  const float* __restrict__ b2,
    float* __restrict__ out, int B)
{
    // layer0 row r=(g*7+j), 12 floats: [wih0[r], b0[r], whh0[r][0..6], pad x3]
    __shared__ __align__(16) float s_l0[28 * 12];
    // layer1 row r, 16 floats: [b1[r], wih1[r][0..6], whh1[r][0..6], pad]
    __shared__ __align__(16) float s_l1[28 * 16];
    __shared__ __align__(16) float s_w1[12];
    __shared__ float s_w2[2 * HH];
    __shared__ float s_b1lin, s_b2;
    // tanh(linear1) per (local batch, t); stride 15 (odd) => conflict-free
    __shared__ float s_u[BPB * 15];

    const int tid = threadIdx.x;

    for (int r = tid; r < 28; r += NTHR) {
        s_l0[r * 12 + 0] = wih0[r];
        s_l0[r * 12 + 1] = bih0[r] + bhh0[r];
#pragma unroll
        for (int k = 0; k < 7; k++) s_l0[r * 12 + 2 + k] = whh0[r * 7 + k];
        s_l0[r * 12 + 9] = 0.f; s_l0[r * 12 + 10] = 0.f; s_l0[r * 12 + 11] = 0.f;

        s_l1[r * 16 + 0] = bih1[r] + bhh1[r];
#pragma unroll
        for (int k = 0; k < 7; k++) s_l1[r * 16 + 1 + k] = wih1[r * 7 + k];
#pragma unroll
        for (int k = 0; k < 7; k++) s_l1[r * 16 + 8 + k] = whh1[r * 7 + k];
        s_l1[r * 16 + 15] = 0.f;
    }
    if (tid < 2 * HH) s_w2[tid] = w2[tid];
    if (tid < FF)     s_w1[tid] = w1[tid];
    if (tid == 0) { s_b1lin = b1[0]; s_b2 = b2[0]; }
    __syncthreads();

    const int blk_base = blockIdx.x * BPB;
    const int nb = min(BPB, B - blk_base);
    const int cnt = nb * TT;

    // ---- phase 1: coalesced linear1 + tanh over 512 local elements ----
    {
        const float blin = s_b1lin;
        float4 wA = *(const float4*)&s_w1[0];
        float4 wB = *(const float4*)&s_w1[4];
        float4 wC = *(const float4*)&s_w1[8];
        const float* xb = x + (long)blk_base * TT * FF;
#pragma unroll 1
        for (int it = 0; it < EB * TT; it++) {
            int idx = it * NTHR + tid;
            if (idx < cnt) {
                int bl = idx / TT;
                int t  = idx - bl * TT;
                const float4* px = (const float4*)(xb + (long)idx * FF);
                float4 a0 = px[0], a1 = px[1], a2 = px[2];
                float s = blin;
                s = fmaf(a0.x, wA.x, s); s = fmaf(a0.y, wA.y, s);
                s = fmaf(a0.z, wA.z, s); s = fmaf(a0.w, wA.w, s);
                s = fmaf(a1.x, wB.x, s); s = fmaf(a1.y, wB.y, s);
                s = fmaf(a1.z, wB.z, s); s = fmaf(a1.w, wB.w, s);
                s = fmaf(a2.x, wC.x, s); s = fmaf(a2.y, wC.y, s);
                s = fmaf(a2.z, wC.z, s); s = fmaf(a2.w, wC.w, s);
                s_u[bl * 15 + t] = tanh_(s);
            }
        }
    }
    __syncthreads();

    if (blk_base + tid >= B) return;

    // u-row index per element (clamped to a valid row if out of range;
    // results for missing elements are simply not stored)
    int ur[EB];
#pragma unroll
    for (int e = 0; e < EB; e++) {
        int le = e * NTHR + tid;
        ur[e] = (le < nb) ? le : tid;
    }

    // ---- phase 2: two stacked LSTM layers x EB batch elements ----
    float h0[EB][HH], c0[EB][HH], h1[EB][HH], c1[EB][HH];
#pragma unroll
    for (int e = 0; e < EB; e++)
#pragma unroll
        for (int j = 0; j < HH; j++) {
            h0[e][j] = 0.f; c0[e][j] = 0.f; h1[e][j] = 0.f; c1[e][j] = 0.f;
        }

#pragma unroll 1
    for (int t = 0; t < TT; t++) {
        float xin[EB];
#pragma unroll
        for (int e = 0; e < EB; e++) xin[e] = s_u[ur[e] * 15 + t];

        // layer 0 (all elements share each weight row load)
        float hn[EB][HH];
#pragma unroll
        for (int j = 0; j < HH; j++) {
            float z[EB][4];
#pragma unroll
            for (int g = 0; g < 4; g++) {
                const float* rp = &s_l0[(g * HH + j) * 12];
                float4 r0 = lds128v(rp);
                float4 r1 = lds128v(rp + 4);
                float  r2 = s_l0[(g * HH + j) * 12 + 8];
#pragma unroll
                for (int e = 0; e < EB; e++) {
                    float zz = fmaf(xin[e], r0.x, r0.y);
                    zz = fmaf(h0[e][0], r0.z, zz);
                    zz = fmaf(h0[e][1], r0.w, zz);
                    zz = fmaf(h0[e][2], r1.x, zz);
                    zz = fmaf(h0[e][3], r1.y, zz);
                    zz = fmaf(h0[e][4], r1.z, zz);
                    zz = fmaf(h0[e][5], r1.w, zz);
                    zz = fmaf(h0[e][6], r2,   zz);
                    z[e][g] = zz;
                }
            }
#pragma unroll
            for (int e = 0; e < EB; e++) {
                float cv = fmaf(sig_(z[e][1]), c0[e][j], sig_(z[e][0]) * tanh_(z[e][2]));
                c0[e][j] = cv;
                hn[e][j] = sig_(z[e][3]) * tanh_(cv);
            }
        }

        // layer 1
        float hn1[EB][HH];
#pragma unroll
        for (int j = 0; j < HH; j++) {
            float z[EB][4];
#pragma unroll
            for (int g = 0; g < 4; g++) {
                const float* rp = &s_l1[(g * HH + j) * 16];
                float4 r0 = lds128v(rp);
                float4 r1 = lds128v(rp + 4);
                float4 r2 = lds128v(rp + 8);
                float4 r3 = lds128v(rp + 12);
#pragma unroll
                for (int e = 0; e < EB; e++) {
                    float zz = r0.x;
                    zz = fmaf(hn[e][0], r0.y, zz);
                    zz = fmaf(hn[e][1], r0.z, zz);
                    zz = fmaf(hn[e][2], r0.w, zz);
                    zz = fmaf(hn[e][3], r1.x, zz);
                    zz = fmaf(hn[e][4], r1.y, zz);
                    zz = fmaf(hn[e][5], r1.z, zz);
                    zz = fmaf(hn[e][6], r1.w, zz);
                    zz = fmaf(h1[e][0], r2.x, zz);
                    zz = fmaf(h1[e][1], r2.y, zz);
                    zz = fmaf(h1[e][2], r2.z, zz);
                    zz = fmaf(h1[e][3], r2.w, zz);
                    zz = fmaf(h1[e][4], r3.x, zz);
                    zz = fmaf(h1[e][5], r3.y, zz);
                    zz = fmaf(h1[e][6], r3.z, zz);
                    z[e][g] = zz;
                }
            }
#pragma unroll
            for (int e = 0; e < EB; e++) {
                float cv = fmaf(sig_(z[e][1]), c1[e][j], sig_(z[e][0]) * tanh_(z[e][2]));
                c1[e][j] = cv;
                hn1[e][j] = sig_(z[e][3]) * tanh_(cv);
            }
        }

#pragma unroll
        for (int e = 0; e < EB; e++)
#pragma unroll
            for (int j = 0; j < HH; j++) {
                h0[e][j] = hn[e][j]; h1[e][j] = hn1[e][j];
            }
    }

    // ---- phase 3 ----
#pragma unroll
    for (int e = 0; e < EB; e++) {
        float acc = s_b2;
#pragma unroll
        for (int j = 0; j < HH; j++) {
            acc = fmaf(h0[e][j], s_w2[j], acc);
            acc = fmaf(h1[e][j], s_w2[HH + j], acc);
        }
        int gb = blk_base + e * NTHR + tid;
        if (gb < B) out[gb] = acc;
    }
}

extern "C" void kernel_launch(void* const* d_in, const int* in_sizes, int n_in,
                              void* d_out, int out_size) {
    const float* x    = (const float*)d_in[0];
    const float* w1   = (const float*)d_in[1];
    const float* b1   = (const float*)d_in[2];
    const float* wih0 = (const float*)d_in[3];
    const float* whh0 = (const float*)d_in[4];
    const float* bih0 = (const float*)d_in[5];
    const float* bhh0 = (const float*)d_in[6];
    const float* wih1 = (const float*)d_in[7];
    const float* whh1 = (const float*)d_in[8];
    const float* bih1 = (const float*)d_in[9];
    const float* bhh1 = (const float*)d_in[10];
    const float* w2   = (const float*)d_in[11];
    const float* b2   = (const float*)d_in[12];
    float* out = (float*)d_out;

    const int B    = out_size;       // 262144
    const int grid = (B + BPB - 1) / BPB;

    lstm_fused_kernel<<<grid, NTHR>>>(x, w1, b1, wih0, whh0, bih0, bhh0,
                                      wih1, whh1, bih1, bhh1, w2, b2,
                                      out, B);
}

// round 9
// speedup vs baseline: 1.3787x; 1.3787x over previous
#include <cuda_runtime.h>
#include <cstdint>

// ---------- hardware tanh (1 MUFU op); sigmoid via tanh identity ----------
__device__ __forceinline__ float tanh_(float x) {
    float r;
    asm("tanh.approx.f32 %0, %1;" : "=f"(r) : "f"(x));
    return r;
}
__device__ __forceinline__ float sig_(float x) {
    return fmaf(0.5f, tanh_(0.5f * x), 0.5f);
}

// volatile LDS.128: uncacheable, unhoistable -> kills ptxas weight-caching
__device__ __forceinline__ float4 lds128v(const float* p) {
    float4 v;
    unsigned saddr = (unsigned)__cvta_generic_to_shared(p);
    asm volatile("ld.volatile.shared.v4.f32 {%0,%1,%2,%3}, [%4];"
                 : "=f"(v.x), "=f"(v.y), "=f"(v.z), "=f"(v.w)
                 : "r"(saddr));
    return v;
}

#define TT 14
#define HH 7
#define FF 12
#define NTHR 128
#define PERMAX 256          // capacity: up to 2 elements per thread
#define GRID_BLOCKS 1184    // = 2 waves x 4 blocks/SM x 148 SMs

__global__ __launch_bounds__(NTHR, 4)
void lstm_fused_kernel(
    const float* __restrict__ x,
    const float* __restrict__ w1,  const float* __restrict__ b1,
    const float* __restrict__ wih0, const float* __restrict__ whh0,
    const float* __restrict__ bih0, const float* __restrict__ bhh0,
    const float* __restrict__ wih1, const float* __restrict__ whh1,
    const float* __restrict__ bih1, const float* __restrict__ bhh1,
    const float* __restrict__ w2,  const float* __restrict__ b2,
    float* __restrict__ out, int B, int per)
{
    // layer0 row r=(g*7+j), 12 floats: [wih0[r], b0[r], whh0[r][0..6], pad x3]
    __shared__ __align__(16) float s_l0[28 * 12];
    // layer1 row r, 16 floats: [b1[r], wih1[r][0..6], whh1[r][0..6], pad]
    __shared__ __align__(16) float s_l1[28 * 16];
    __shared__ __align__(16) float s_w1[12];
    __shared__ float s_w2[2 * HH];
    __shared__ float s_b1lin, s_b2;
    // tanh(linear1) per (local batch, t); stride 15 (odd) => conflict-free
    __shared__ float s_u[PERMAX * 15];

    const int tid = threadIdx.x;

    for (int r = tid; r < 28; r += NTHR) {
        s_l0[r * 12 + 0] = wih0[r];
        s_l0[r * 12 + 1] = bih0[r] + bhh0[r];
#pragma unroll
        for (int k = 0; k < 7; k++) s_l0[r * 12 + 2 + k] = whh0[r * 7 + k];
        s_l0[r * 12 + 9] = 0.f; s_l0[r * 12 + 10] = 0.f; s_l0[r * 12 + 11] = 0.f;

        s_l1[r * 16 + 0] = bih1[r] + bhh1[r];
#pragma unroll
        for (int k = 0; k < 7; k++) s_l1[r * 16 + 1 + k] = wih1[r * 7 + k];
#pragma unroll
        for (int k = 0; k < 7; k++) s_l1[r * 16 + 8 + k] = whh1[r * 7 + k];
        s_l1[r * 16 + 15] = 0.f;
    }
    if (tid < 2 * HH) s_w2[tid] = w2[tid];
    if (tid < FF)     s_w1[tid] = w1[tid];
    if (tid == 0) { s_b1lin = b1[0]; s_b2 = b2[0]; }
    __syncthreads();

    const int blk_base = blockIdx.x * per;
    const int nb = min(per, B - blk_base);   // may be <= 0 for trailing blocks
    if (nb <= 0) return;                     // uniform across block (after sync)
    const int cnt = nb * TT;

    // ---- phase 1: coalesced linear1 + tanh over nb local elements ----
    {
        const float blin = s_b1lin;
        float4 wA = *(const float4*)&s_w1[0];
        float4 wB = *(const float4*)&s_w1[4];
        float4 wC = *(const float4*)&s_w1[8];
        const float* xb = x + (long)blk_base * TT * FF;
        const int iters = (cnt + NTHR - 1) / NTHR;
#pragma unroll 1
        for (int it = 0; it < iters; it++) {
            int idx = it * NTHR + tid;
            if (idx < cnt) {
                int bl = idx / TT;
                int t  = idx - bl * TT;
                const float4* px = (const float4*)(xb + (long)idx * FF);
                float4 a0 = px[0], a1 = px[1], a2 = px[2];
                float s = blin;
                s = fmaf(a0.x, wA.x, s); s = fmaf(a0.y, wA.y, s);
                s = fmaf(a0.z, wA.z, s); s = fmaf(a0.w, wA.w, s);
                s = fmaf(a1.x, wB.x, s); s = fmaf(a1.y, wB.y, s);
                s = fmaf(a1.z, wB.z, s); s = fmaf(a1.w, wB.w, s);
                s = fmaf(a2.x, wC.x, s); s = fmaf(a2.y, wC.y, s);
                s = fmaf(a2.z, wC.z, s); s = fmaf(a2.w, wC.w, s);
                s_u[bl * 15 + t] = tanh_(s);
            }
        }
    }
    __syncthreads();

    const bool hasA = (tid < nb);
    const bool hasB = (NTHR + tid < nb);
    if (!hasA) return;
    const int uA = tid;
    const int uB = hasB ? (NTHR + tid) : tid;

    // ---- phase 2: two stacked LSTM layers x two batch elements ----
    float h0A[HH], c0A[HH], h1A[HH], c1A[HH];
    float h0B[HH], c0B[HH], h1B[HH], c1B[HH];
#pragma unroll
    for (int j = 0; j < HH; j++) {
        h0A[j] = 0.f; c0A[j] = 0.f; h1A[j] = 0.f; c1A[j] = 0.f;
        h0B[j] = 0.f; c0B[j] = 0.f; h1B[j] = 0.f; c1B[j] = 0.f;
    }

#pragma unroll 1
    for (int t = 0; t < TT; t++) {
        const float xinA = s_u[uA * 15 + t];
        const float xinB = s_u[uB * 15 + t];

        // layer 0 (both elements share each weight row load)
        float hnA[HH], hnB[HH];
#pragma unroll
        for (int j = 0; j < HH; j++) {
            float zA[4], zB[4];
#pragma unroll
            for (int g = 0; g < 4; g++) {
                const float* rp = &s_l0[(g * HH + j) * 12];
                float4 r0 = lds128v(rp);
                float4 r1 = lds128v(rp + 4);
                float  r2 = s_l0[(g * HH + j) * 12 + 8];
                float a = fmaf(xinA, r0.x, r0.y);
                float bq = fmaf(xinB, r0.x, r0.y);
                a  = fmaf(h0A[0], r0.z, a);  bq = fmaf(h0B[0], r0.z, bq);
                a  = fmaf(h0A[1], r0.w, a);  bq = fmaf(h0B[1], r0.w, bq);
                a  = fmaf(h0A[2], r1.x, a);  bq = fmaf(h0B[2], r1.x, bq);
                a  = fmaf(h0A[3], r1.y, a);  bq = fmaf(h0B[3], r1.y, bq);
                a  = fmaf(h0A[4], r1.z, a);  bq = fmaf(h0B[4], r1.z, bq);
                a  = fmaf(h0A[5], r1.w, a);  bq = fmaf(h0B[5], r1.w, bq);
                a  = fmaf(h0A[6], r2,   a);  bq = fmaf(h0B[6], r2,   bq);
                zA[g] = a; zB[g] = bq;
            }
            float cvA = fmaf(sig_(zA[1]), c0A[j], sig_(zA[0]) * tanh_(zA[2]));
            float cvB = fmaf(sig_(zB[1]), c0B[j], sig_(zB[0]) * tanh_(zB[2]));
            c0A[j] = cvA; c0B[j] = cvB;
            hnA[j] = sig_(zA[3]) * tanh_(cvA);
            hnB[j] = sig_(zB[3]) * tanh_(cvB);
        }

        // layer 1
        float hn1A[HH], hn1B[HH];
#pragma unroll
        for (int j = 0; j < HH; j++) {
            float zA[4], zB[4];
#pragma unroll
            for (int g = 0; g < 4; g++) {
                const float* rp = &s_l1[(g * HH + j) * 16];
                float4 r0 = lds128v(rp);
                float4 r1 = lds128v(rp + 4);
                float4 r2 = lds128v(rp + 8);
                float4 r3 = lds128v(rp + 12);
                float a = r0.x, bq = r0.x;
                a = fmaf(hnA[0], r0.y, a);  bq = fmaf(hnB[0], r0.y, bq);
                a = fmaf(hnA[1], r0.z, a);  bq = fmaf(hnB[1], r0.z, bq);
                a = fmaf(hnA[2], r0.w, a);  bq = fmaf(hnB[2], r0.w, bq);
                a = fmaf(hnA[3], r1.x, a);  bq = fmaf(hnB[3], r1.x, bq);
                a = fmaf(hnA[4], r1.y, a);  bq = fmaf(hnB[4], r1.y, bq);
                a = fmaf(hnA[5], r1.z, a);  bq = fmaf(hnB[5], r1.z, bq);
                a = fmaf(hnA[6], r1.w, a);  bq = fmaf(hnB[6], r1.w, bq);
                a = fmaf(h1A[0], r2.x, a);  bq = fmaf(h1B[0], r2.x, bq);
                a = fmaf(h1A[1], r2.y, a);  bq = fmaf(h1B[1], r2.y, bq);
                a = fmaf(h1A[2], r2.z, a);  bq = fmaf(h1B[2], r2.z, bq);
                a = fmaf(h1A[3], r2.w, a);  bq = fmaf(h1B[3], r2.w, bq);
                a = fmaf(h1A[4], r3.x, a);  bq = fmaf(h1B[4], r3.x, bq);
                a = fmaf(h1A[5], r3.y, a);  bq = fmaf(h1B[5], r3.y, bq);
                a = fmaf(h1A[6], r3.z, a);  bq = fmaf(h1B[6], r3.z, bq);
                zA[g] = a; zB[g] = bq;
            }
            float cvA = fmaf(sig_(zA[1]), c1A[j], sig_(zA[0]) * tanh_(zA[2]));
            float cvB = fmaf(sig_(zB[1]), c1B[j], sig_(zB[0]) * tanh_(zB[2]));
            c1A[j] = cvA; c1B[j] = cvB;
            hn1A[j] = sig_(zA[3]) * tanh_(cvA);
            hn1B[j] = sig_(zB[3]) * tanh_(cvB);
        }

#pragma unroll
        for (int j = 0; j < HH; j++) {
            h0A[j] = hnA[j]; h1A[j] = hn1A[j];
            h0B[j] = hnB[j]; h1B[j] = hn1B[j];
        }
    }

    // ---- phase 3 ----
    float accA = s_b2, accB = s_b2;
#pragma unroll
    for (int j = 0; j < HH; j++) {
        accA = fmaf(h0A[j], s_w2[j], accA);
        accA = fmaf(h1A[j], s_w2[HH + j], accA);
        accB = fmaf(h0B[j], s_w2[j], accB);
        accB = fmaf(h1B[j], s_w2[HH + j], accB);
    }
    out[blk_base + tid] = accA;
    if (hasB) out[blk_base + NTHR + tid] = accB;
}

extern "C" void kernel_launch(void* const* d_in, const int* in_sizes, int n_in,
                              void* d_out, int out_size) {
    const float* x    = (const float*)d_in[0];
    const float* w1   = (const float*)d_in[1];
    const float* b1   = (const float*)d_in[2];
    const float* wih0 = (const float*)d_in[3];
    const float* whh0 = (const float*)d_in[4];
    const float* bih0 = (const float*)d_in[5];
    const float* bhh0 = (const float*)d_in[6];
    const float* wih1 = (const float*)d_in[7];
    const float* whh1 = (const float*)d_in[8];
    const float* bih1 = (const float*)d_in[9];
    const float* bhh1 = (const float*)d_in[10];
    const float* w2   = (const float*)d_in[11];
    const float* b2   = (const float*)d_in[12];
    float* out = (float*)d_out;

    const int B   = out_size;                        // 262144
    int per = (B + GRID_BLOCKS - 1) / GRID_BLOCKS;   // 222
    if (per > PERMAX) per = PERMAX;                  // safety (B larger than expected)
    int grid = (B + per - 1) / per;                  // <= GRID_BLOCKS

    lstm_fused_kernel<<<grid, NTHR>>>(x, w1, b1, wih0, whh0, bih0, bhh0,
                                      wih1, whh1, bih1, bhh1, w2, b2,
                                      out, B, per);
}

// round 10
// speedup vs baseline: 1.4883x; 1.0796x over previous
#include <cuda_runtime.h>
#include <cstdint>

// ---------- hardware tanh (1 MUFU op); sigmoid via tanh identity ----------
__device__ __forceinline__ float tanh_(float x) {
    float r;
    asm("tanh.approx.f32 %0, %1;" : "=f"(r) : "f"(x));
    return r;
}
__device__ __forceinline__ float sig_(float x) {
    return fmaf(0.5f, tanh_(0.5f * x), 0.5f);
}

// volatile LDS.128: uncacheable, unhoistable -> kills ptxas weight-caching
__device__ __forceinline__ float4 lds128v(const float* p) {
    float4 v;
    unsigned saddr = (unsigned)__cvta_generic_to_shared(p);
    asm volatile("ld.volatile.shared.v4.f32 {%0,%1,%2,%3}, [%4];"
                 : "=f"(v.x), "=f"(v.y), "=f"(v.z), "=f"(v.w)
                 : "r"(saddr));
    return v;
}

#define TT 14
#define HH 7
#define FF 12
#define NTHR 128

// EB-templated block body: EB=1 compiles with NO second chain.
template <int EB>
__device__ __forceinline__ void run_block(
    const float* __restrict__ x, float* __restrict__ out, int B, int base,
    const float* s_l0, const float* s_l1, const float* s_w1,
    const float* s_w2, float blin, float b2v, float* s_u, int tid)
{
    const int cap = EB * NTHR;
    const int nb = min(cap, B - base);   // block-uniform
    if (nb <= 0) return;
    const int cnt = nb * TT;

    // ---- phase 1: coalesced linear1 + tanh ----
    {
        float4 wA = *(const float4*)&s_w1[0];
        float4 wB = *(const float4*)&s_w1[4];
        float4 wC = *(const float4*)&s_w1[8];
        const float* xb = x + (long)base * TT * FF;
        const int iters = (cnt + NTHR - 1) / NTHR;
#pragma unroll 1
        for (int it = 0; it < iters; it++) {
            int idx = it * NTHR + tid;
            if (idx < cnt) {
                int bl = idx / TT;
                int t  = idx - bl * TT;
                const float4* px = (const float4*)(xb + (long)idx * FF);
                float4 a0 = px[0], a1 = px[1], a2 = px[2];
                float s = blin;
                s = fmaf(a0.x, wA.x, s); s = fmaf(a0.y, wA.y, s);
                s = fmaf(a0.z, wA.z, s); s = fmaf(a0.w, wA.w, s);
                s = fmaf(a1.x, wB.x, s); s = fmaf(a1.y, wB.y, s);
                s = fmaf(a1.z, wB.z, s); s = fmaf(a1.w, wB.w, s);
                s = fmaf(a2.x, wC.x, s); s = fmaf(a2.y, wC.y, s);
                s = fmaf(a2.z, wC.z, s); s = fmaf(a2.w, wC.w, s);
                s_u[bl * 15 + t] = tanh_(s);
            }
        }
    }
    __syncthreads();

    if (tid >= nb) return;

    int ur[EB];
#pragma unroll
    for (int e = 0; e < EB; e++) ur[e] = min(e * NTHR + tid, nb - 1);

    float h0[EB][HH], c0[EB][HH], h1[EB][HH], c1[EB][HH];
#pragma unroll
    for (int e = 0; e < EB; e++)
#pragma unroll
        for (int j = 0; j < HH; j++) {
            h0[e][j] = 0.f; c0[e][j] = 0.f; h1[e][j] = 0.f; c1[e][j] = 0.f;
        }

#pragma unroll 1
    for (int t = 0; t < TT; t++) {
        float xin[EB];
#pragma unroll
        for (int e = 0; e < EB; e++) xin[e] = s_u[ur[e] * 15 + t];

        // ---- layer 0: per j, merged record [b_i,b_f,b_g,b_o | 4 x (wih, whh0..6)]
        float hn[EB][HH];
#pragma unroll
        for (int j = 0; j < HH; j++) {
            const float* rec = &s_l0[j * 36];
            float4 bz = lds128v(rec);
            const float bsel[4] = {bz.x, bz.y, bz.z, bz.w};
            float z[EB][4];
#pragma unroll
            for (int g = 0; g < 4; g++) {
                float4 r0 = lds128v(rec + 4 + g * 8);
                float4 r1 = lds128v(rec + 8 + g * 8);
#pragma unroll
                for (int e = 0; e < EB; e++) {
                    float zz = fmaf(xin[e], r0.x, bsel[g]);
                    zz = fmaf(h0[e][0], r0.y, zz);
                    zz = fmaf(h0[e][1], r0.z, zz);
                    zz = fmaf(h0[e][2], r0.w, zz);
                    zz = fmaf(h0[e][3], r1.x, zz);
                    zz = fmaf(h0[e][4], r1.y, zz);
                    zz = fmaf(h0[e][5], r1.z, zz);
                    zz = fmaf(h0[e][6], r1.w, zz);
                    z[e][g] = zz;
                }
            }
#pragma unroll
            for (int e = 0; e < EB; e++) {
                float cv = fmaf(sig_(z[e][1]), c0[e][j], sig_(z[e][0]) * tanh_(z[e][2]));
                c0[e][j] = cv;
                hn[e][j] = sig_(z[e][3]) * tanh_(cv);
            }
        }

        // ---- layer 1: row r = g*7+j, 16 floats [b, wih0..6, whh0..6, pad]
        float hn1[EB][HH];
#pragma unroll
        for (int j = 0; j < HH; j++) {
            float z[EB][4];
#pragma unroll
            for (int g = 0; g < 4; g++) {
                const float* rp = &s_l1[(g * HH + j) * 16];
                float4 r0 = lds128v(rp);
                float4 r1 = lds128v(rp + 4);
                float4 r2 = lds128v(rp + 8);
                float4 r3 = lds128v(rp + 12);
#pragma unroll
                for (int e = 0; e < EB; e++) {
                    float zz = r0.x;
                    zz = fmaf(hn[e][0], r0.y, zz);
                    zz = fmaf(hn[e][1], r0.z, zz);
                    zz = fmaf(hn[e][2], r0.w, zz);
                    zz = fmaf(hn[e][3], r1.x, zz);
                    zz = fmaf(hn[e][4], r1.y, zz);
                    zz = fmaf(hn[e][5], r1.z, zz);
                    zz = fmaf(hn[e][6], r1.w, zz);
                    zz = fmaf(h1[e][0], r2.x, zz);
                    zz = fmaf(h1[e][1], r2.y, zz);
                    zz = fmaf(h1[e][2], r2.z, zz);
                    zz = fmaf(h1[e][3], r2.w, zz);
                    zz = fmaf(h1[e][4], r3.x, zz);
                    zz = fmaf(h1[e][5], r3.y, zz);
                    zz = fmaf(h1[e][6], r3.z, zz);
                    z[e][g] = zz;
                }
            }
#pragma unroll
            for (int e = 0; e < EB; e++) {
                float cv = fmaf(sig_(z[e][1]), c1[e][j], sig_(z[e][0]) * tanh_(z[e][2]));
                c1[e][j] = cv;
                hn1[e][j] = sig_(z[e][3]) * tanh_(cv);
            }
        }

#pragma unroll
        for (int e = 0; e < EB; e++)
#pragma unroll
            for (int j = 0; j < HH; j++) {
                h0[e][j] = hn[e][j]; h1[e][j] = hn1[e][j];
            }
    }

    // ---- phase 3 ----
#pragma unroll
    for (int e = 0; e < EB; e++) {
        float acc = b2v;
#pragma unroll
        for (int j = 0; j < HH; j++) {
            acc = fmaf(h0[e][j], s_w2[j], acc);
            acc = fmaf(h1[e][j], s_w2[HH + j], acc);
        }
        int gb = base + e * NTHR + tid;
        if (gb < B) out[gb] = acc;
    }
}

__global__ __launch_bounds__(NTHR, 4)
void lstm_fused_kernel(
    const float* __restrict__ x,
    const float* __restrict__ w1,  const float* __restrict__ b1,
    const float* __restrict__ wih0, const float* __restrict__ whh0,
    const float* __restrict__ bih0, const float* __restrict__ bhh0,
    const float* __restrict__ wih1, const float* __restrict__ whh1,
    const float* __restrict__ bih1, const float* __restrict__ bhh1,
    const float* __restrict__ w2,  const float* __restrict__ b2,
    float* __restrict__ out, int B, int nfull)
{
    // layer0 per-j record: 36 floats [4 biases][4 x (wih, whh0..6)]
    __shared__ __align__(16) float s_l0[HH * 36];
    // layer1 row r, 16 floats: [b1[r], wih1[r][0..6], whh1[r][0..6], pad]
    __shared__ __align__(16) float s_l1[28 * 16];
    __shared__ __align__(16) float s_w1[12];
    __shared__ float s_w2[2 * HH];
    __shared__ float s_b1lin, s_b2;
    __shared__ float s_u[2 * NTHR * 15];

    const int tid = threadIdx.x;

    for (int r = tid; r < 28; r += NTHR) {
        int g = r / 7, j = r % 7;
        s_l0[j * 36 + g] = bih0[r] + bhh0[r];
        s_l0[j * 36 + 4 + g * 8 + 0] = wih0[r];
#pragma unroll
        for (int k = 0; k < 7; k++) s_l0[j * 36 + 4 + g * 8 + 1 + k] = whh0[r * 7 + k];

        s_l1[r * 16 + 0] = bih1[r] + bhh1[r];
#pragma unroll
        for (int k = 0; k < 7; k++) s_l1[r * 16 + 1 + k] = wih1[r * 7 + k];
#pragma unroll
        for (int k = 0; k < 7; k++) s_l1[r * 16 + 8 + k] = whh1[r * 7 + k];
        s_l1[r * 16 + 15] = 0.f;
    }
    if (tid < 2 * HH) s_w2[tid] = w2[tid];
    if (tid < FF)     s_w1[tid] = w1[tid];
    if (tid == 0) { s_b1lin = b1[0]; s_b2 = b2[0]; }
    __syncthreads();

    const int bid = blockIdx.x;
    if (bid < nfull) {
        run_block<2>(x, out, B, bid * (2 * NTHR),
                     s_l0, s_l1, s_w1, s_w2, s_b1lin, s_b2, s_u, tid);
    } else {
        run_block<1>(x, out, B, nfull * (2 * NTHR) + (bid - nfull) * NTHR,
                     s_l0, s_l1, s_w1, s_w2, s_b1lin, s_b2, s_u, tid);
    }
}

extern "C" void kernel_launch(void* const* d_in, const int* in_sizes, int n_in,
                              void* d_out, int out_size) {
    const float* x    = (const float*)d_in[0];
    const float* w1   = (const float*)d_in[1];
    const float* b1   = (const float*)d_in[2];
    const float* wih0 = (const float*)d_in[3];
    const float* whh0 = (const float*)d_in[4];
    const float* bih0 = (const float*)d_in[5];
    const float* bhh0 = (const float*)d_in[6];
    const float* wih1 = (const float*)d_in[7];
    const float* whh1 = (const float*)d_in[8];
    const float* bih1 = (const float*)d_in[9];
    const float* bhh1 = (const float*)d_in[10];
    const float* w2   = (const float*)d_in[11];
    const float* b2   = (const float*)d_in[12];
    float* out = (float*)d_out;

    const int B = out_size;                 // 262144

    int sms = 148;
    cudaDeviceGetAttribute(&sms, cudaDevAttrMultiProcessorCount, 0);

    // 2 full waves at 4 blocks/SM; full blocks (2 chains) + light blocks (1 chain)
    int grid   = 2 * 4 * sms;                     // 1216 on GB300 (152 SMs)
    int chunks = (B + NTHR - 1) / NTHR;           // 2048 chunks of 128
    if (chunks > 2 * grid) grid = (chunks + 1) / 2;  // safety for huge B
    int nfull = chunks - grid;                    // 832 on GB300
    if (nfull < 0) nfull = 0;
    if (nfull > grid) nfull = grid;

    lstm_fused_kernel<<<grid, NTHR>>>(x, w1, b1, wih0, whh0, bih0, bhh0,
                                      wih1, whh1, bih1, bhh1, w2, b2,
                                      out, B, nfull);
}